// round 1
// baseline (speedup 1.0000x reference)
#include <cuda_runtime.h>
#include <cstdint>
#include <cstddef>

#define OUT_FEAT 11008
#define IN_FEAT  4096
#define HAD      128
#define NBLK     (OUT_FEAT / HAD)   // 86
#define NTILE_N  (IN_FEAT / 128)    // 32

// 180 MB scratch for W = blockdiag(R_right^T) @ inp   (alloc-free rule: device global)
__device__ float g_W[(size_t)OUT_FEAT * (size_t)IN_FEAT];
__device__ unsigned int g_absmax_bits;

__global__ void k_init() {
    if (threadIdx.x == 0) g_absmax_bits = 0u;
}

// ---------------------------------------------------------------------------
// Kernel 1: rotation.  W[b*128+h, k] = sum_d R_right[d,h] * inp[b*128+d, k]
// Per CTA: 128(h) x 128(k) output tile, K=128 (d), BK=8, 8x8 per thread.
// ---------------------------------------------------------------------------
__global__ __launch_bounds__(256) void k_rotate(const float* __restrict__ inp,
                                                const float* __restrict__ Rr) {
    __shared__ float As[8][128];   // As[d][h] = Rr[d*128 + h]
    __shared__ float Bs[8][128];   // Bs[d][k] = inp[(b*128+d)*IN + nt*128 + k]

    const int b   = blockIdx.y;    // 0..85
    const int nt  = blockIdx.x;    // 0..31
    const int tid = threadIdx.x;
    const int ty  = tid >> 4;      // 0..15
    const int tx  = tid & 15;      // 0..15
    const int ldR = tid >> 5;      // 0..7
    const int ldC = (tid & 31) << 2;

    const float* Bg = inp + ((size_t)b * HAD) * IN_FEAT + (size_t)nt * 128;

    float acc[8][8];
    #pragma unroll
    for (int i = 0; i < 8; i++)
        #pragma unroll
        for (int j = 0; j < 8; j++) acc[i][j] = 0.0f;

    float4 a_nxt = *(const float4*)&Rr[(size_t)ldR * HAD + ldC];
    float4 b_nxt = *(const float4*)&Bg[(size_t)ldR * IN_FEAT + ldC];

    for (int d0 = 0; d0 < HAD; d0 += 8) {
        *(float4*)&As[ldR][ldC] = a_nxt;
        *(float4*)&Bs[ldR][ldC] = b_nxt;
        __syncthreads();
        if (d0 + 8 < HAD) {
            a_nxt = *(const float4*)&Rr[(size_t)(d0 + 8 + ldR) * HAD + ldC];
            b_nxt = *(const float4*)&Bg[(size_t)(d0 + 8 + ldR) * IN_FEAT + ldC];
        }
        #pragma unroll
        for (int d = 0; d < 8; d++) {
            float a[8], bb[8];
            *(float4*)&a[0]  = *(float4*)&As[d][ty * 8];
            *(float4*)&a[4]  = *(float4*)&As[d][ty * 8 + 4];
            *(float4*)&bb[0] = *(float4*)&Bs[d][tx * 8];
            *(float4*)&bb[4] = *(float4*)&Bs[d][tx * 8 + 4];
            #pragma unroll
            for (int i = 0; i < 8; i++)
                #pragma unroll
                for (int j = 0; j < 8; j++)
                    acc[i][j] = fmaf(a[i], bb[j], acc[i][j]);
        }
        __syncthreads();
    }

    float* Cg = g_W + ((size_t)(b * HAD + ty * 8)) * IN_FEAT + (size_t)nt * 128 + tx * 8;
    #pragma unroll
    for (int i = 0; i < 8; i++) {
        *(float4*)&Cg[(size_t)i * IN_FEAT]     = make_float4(acc[i][0], acc[i][1], acc[i][2], acc[i][3]);
        *(float4*)&Cg[(size_t)i * IN_FEAT + 4] = make_float4(acc[i][4], acc[i][5], acc[i][6], acc[i][7]);
    }
}

// ---------------------------------------------------------------------------
// Kernel 2: main GEMM.  Y[M=11008, N=4096] = W[M, K=4096] @ R_left[K, N]
// 128x128 tile, BK=8, 8x8 per thread, global->reg prefetch.
// Epilogue: write Y to d_out, CTA |max| reduce, atomicMax into g_absmax_bits.
// ---------------------------------------------------------------------------
__global__ __launch_bounds__(256) void k_gemm(const float* __restrict__ B,
                                              float* __restrict__ C) {
    __shared__ float As[8][128];   // As[k][m]  (A transposed in smem)
    __shared__ float Bs[8][128];   // Bs[k][n]
    __shared__ float red[8];

    const int bm  = blockIdx.y;    // 0..85
    const int bn  = blockIdx.x;    // 0..31
    const int tid = threadIdx.x;
    const int ty  = tid >> 4;
    const int tx  = tid & 15;

    const int aRow = tid >> 1;           // 0..127
    const int aCol = (tid & 1) << 2;     // 0 or 4
    const int bRow = tid >> 5;           // 0..7
    const int bCol = (tid & 31) << 2;    // 0..124

    const float* Ag = g_W + ((size_t)bm * 128) * IN_FEAT;
    const float* Bg = B + (size_t)bn * 128;

    float acc[8][8];
    #pragma unroll
    for (int i = 0; i < 8; i++)
        #pragma unroll
        for (int j = 0; j < 8; j++) acc[i][j] = 0.0f;

    float4 a_nxt = *(const float4*)&Ag[(size_t)aRow * IN_FEAT + aCol];
    float4 b_nxt = *(const float4*)&Bg[(size_t)bRow * IN_FEAT + bCol];

    for (int k0 = 0; k0 < IN_FEAT; k0 += 8) {
        As[aCol + 0][aRow] = a_nxt.x;
        As[aCol + 1][aRow] = a_nxt.y;
        As[aCol + 2][aRow] = a_nxt.z;
        As[aCol + 3][aRow] = a_nxt.w;
        *(float4*)&Bs[bRow][bCol] = b_nxt;
        __syncthreads();
        if (k0 + 8 < IN_FEAT) {
            a_nxt = *(const float4*)&Ag[(size_t)aRow * IN_FEAT + (k0 + 8) + aCol];
            b_nxt = *(const float4*)&Bg[(size_t)(k0 + 8 + bRow) * IN_FEAT + bCol];
        }
        #pragma unroll
        for (int k = 0; k < 8; k++) {
            float a[8], bb[8];
            *(float4*)&a[0]  = *(float4*)&As[k][ty * 8];
            *(float4*)&a[4]  = *(float4*)&As[k][ty * 8 + 4];
            *(float4*)&bb[0] = *(float4*)&Bs[k][tx * 8];
            *(float4*)&bb[4] = *(float4*)&Bs[k][tx * 8 + 4];
            #pragma unroll
            for (int i = 0; i < 8; i++)
                #pragma unroll
                for (int j = 0; j < 8; j++)
                    acc[i][j] = fmaf(a[i], bb[j], acc[i][j]);
        }
        __syncthreads();
    }

    // per-thread abs-max
    float m = 0.0f;
    #pragma unroll
    for (int i = 0; i < 8; i++)
        #pragma unroll
        for (int j = 0; j < 8; j++)
            m = fmaxf(m, fabsf(acc[i][j]));
    #pragma unroll
    for (int off = 16; off > 0; off >>= 1)
        m = fmaxf(m, __shfl_xor_sync(0xFFFFFFFFu, m, off));
    if ((tid & 31) == 0) red[tid >> 5] = m;
    __syncthreads();
    if (tid == 0) {
        float mm = red[0];
        #pragma unroll
        for (int w = 1; w < 8; w++) mm = fmaxf(mm, red[w]);
        atomicMax(&g_absmax_bits, __float_as_uint(mm));
    }

    // store Y (pre-quant) to d_out
    float* Cg = C + ((size_t)(bm * 128 + ty * 8)) * IN_FEAT + (size_t)bn * 128 + tx * 8;
    #pragma unroll
    for (int i = 0; i < 8; i++) {
        *(float4*)&Cg[(size_t)i * IN_FEAT]     = make_float4(acc[i][0], acc[i][1], acc[i][2], acc[i][3]);
        *(float4*)&Cg[(size_t)i * IN_FEAT + 4] = make_float4(acc[i][4], acc[i][5], acc[i][6], acc[i][7]);
    }
}

// ---------------------------------------------------------------------------
// Kernel 3: fake-quant in place.  s = max(absmax/127, tiny);
// y = clip(rint(x/s), -127, 127) * s   (rint = round-half-even, matches jnp.round)
// ---------------------------------------------------------------------------
__global__ __launch_bounds__(256) void k_quant(float* __restrict__ y) {
    const float am = __uint_as_float(g_absmax_bits);
    const float s  = fmaxf(am * (1.0f / 127.0f), 1.17549435e-38f);
    size_t idx = (size_t)blockIdx.x * blockDim.x + threadIdx.x;
    float4 v = ((const float4*)y)[idx];
    float4 r;
    r.x = fminf(fmaxf(rintf(v.x / s), -127.0f), 127.0f) * s;
    r.y = fminf(fmaxf(rintf(v.y / s), -127.0f), 127.0f) * s;
    r.z = fminf(fmaxf(rintf(v.z / s), -127.0f), 127.0f) * s;
    r.w = fminf(fmaxf(rintf(v.w / s), -127.0f), 127.0f) * s;
    ((float4*)y)[idx] = r;
}

// ---------------------------------------------------------------------------
extern "C" void kernel_launch(void* const* d_in, const int* in_sizes, int n_in,
                              void* d_out, int out_size) {
    const float* inp    = (const float*)d_in[0];   // (11008, 4096)
    const float* R_left = (const float*)d_in[1];   // (4096, 4096)
    const float* R_right= (const float*)d_in[2];   // (128, 128)
    float* out = (float*)d_out;                    // (11008, 4096)

    k_init<<<1, 32>>>();
    k_rotate<<<dim3(NTILE_N, NBLK), 256>>>(inp, R_right);
    k_gemm<<<dim3(NTILE_N, NBLK), 256>>>(R_left, out);

    const size_t n4 = ((size_t)OUT_FEAT * IN_FEAT) / 4;   // 11,272,192
    k_quant<<<(unsigned)(n4 / 256), 256>>>(out);           // exact multiple
}